// round 16
// baseline (speedup 1.0000x reference)
#include <cuda_runtime.h>
#include <cuda_fp16.h>
#include <stdint.h>

#define D1    256
#define D2    256
#define ODIM  1024
#define BB    64
#define SS    128
#define KTOT  (D1 * D2)       // 65536

// ---------------- stage-1 (tp) config ----------------
#define NCH1  8               // s-chunks of 16
#define CHS1  16
#define PF    260             // F smem pitch (floats), 256 d + 4 pad
#define PR    132             // R smem pitch (floats), 128 e + 4 pad
#define BUF_WORDS (CHS1 * PF + CHS1 * PR)   // 6272
#define NBUF  4
#define SMEM1 (NBUF * BUF_WORDS * 4)        // 100352 B

// ---------------- stage-2 mma config ----------------
#define KS2   18
#define NT2   128
#define KC2   64              // k per stage (doubled: halves sync/loop overhead)
#define STG   3
#define PRE   2

#define A2_BYTES  (64 * 144)           // A: 64 rows x (64 f16 = 128B + pad)
#define B2_BYTES  (128 * 272)          // B: 128 rows x (64 f32 = 256B + pad)
#define STAGE_B   (A2_BYTES + B2_BYTES)          // 44032
#define SMEM2     (STG * STAGE_B)                // 132096

// Device-global scratch
__device__ __half g_tp[(size_t)BB * KTOT];

// ---------------------------------------------------------------------------
// helpers
// ---------------------------------------------------------------------------
__device__ __forceinline__ uint32_t smem_u32(const void* p) {
    uint32_t a;
    asm("{ .reg .u64 t; cvta.to.shared.u64 t, %1; cvt.u32.u64 %0, t; }" : "=r"(a) : "l"(p));
    return a;
}
__device__ __forceinline__ uint32_t pack_h2(float lo, float hi) {
    uint32_t r;
    asm("cvt.rn.f16x2.f32 %0, %1, %2;" : "=r"(r) : "f"(hi), "f"(lo));
    return r;
}
__device__ __forceinline__ void cp16(uint32_t dst, const void* src) {
    asm volatile("cp.async.cg.shared.global [%0], [%1], 16;" :: "r"(dst), "l"(src));
}
__device__ __forceinline__ void hmma(float* c, const uint32_t* a, const uint32_t* b) {
    asm volatile(
        "mma.sync.aligned.m16n8k16.row.col.f32.f16.f16.f32 "
        "{%0,%1,%2,%3}, {%4,%5,%6,%7}, {%8,%9}, {%0,%1,%2,%3};"
        : "+f"(c[0]), "+f"(c[1]), "+f"(c[2]), "+f"(c[3])
        : "r"(a[0]), "r"(a[1]), "r"(a[2]), "r"(a[3]), "r"(b[0]), "r"(b[1]));
}

// ---------------------------------------------------------------------------
// Stage 1: tp[b, d, e] = sum_s F[fillers[b,s], d] * R[roles[b,s], e]
// grid (e-half=2, b=64) = 128 CTAs, 256 thr (8 warps: 4 d-tiles x 2 e-tiles).
// Prologue also initializes out[.] = bias[.] (512 floats per CTA).
// (byte-identical to the proven R14 kernel)
// ---------------------------------------------------------------------------
__global__ __launch_bounds__(256, 1) void tp_mma(
    const int*   __restrict__ fillers,
    const int*   __restrict__ roles,
    const float* __restrict__ ftab,
    const float* __restrict__ rtab,
    const float* __restrict__ bias,
    float*       __restrict__ out)
{
    extern __shared__ float sm1[];
    __shared__ int s_fi[SS];
    __shared__ int s_ri[SS];

    const int b   = blockIdx.y;
    const int e0  = blockIdx.x * 128;
    const int tid = threadIdx.x;
    const int wid  = tid >> 5;
    const int lane = tid & 31;

    if (tid < SS) s_fi[tid]      = fillers[b * SS + tid];
    else          s_ri[tid - SS] = roles[b * SS + (tid - SS)];

    // bias-init of out: 128 CTAs x 512 floats = 64K floats
    if (tid < 128) {
        const int cta = b * 2 + blockIdx.x;       // 0..127
        const int idx = cta * 512 + tid * 4;
        *(float4*)(out + idx) = *(const float4*)(bias + (idx & (ODIM - 1)));
    }
    __syncthreads();

    // staging: 16 rows/chunk, 16 thr/row; F row = 64 x 16B, R row = 32 x 16B
    const int rw = tid >> 4;     // 0..15
    const int cc = tid & 15;

    auto load_chunk = [&](int ch) {
        if (ch < NCH1) {
            float* dstF = sm1 + (ch & 3) * BUF_WORDS;
            float* dstR = dstF + CHS1 * PF;
            const int s = ch * CHS1 + rw;
            const float* fr = ftab + (size_t)s_fi[s] * D1;
            const uint32_t dF = smem_u32(dstF + rw * PF);
            #pragma unroll
            for (int q = 0; q < 4; q++) {
                const int c = cc + 16 * q;          // 0..63
                cp16(dF + c * 16, fr + c * 4);
            }
            const float* rr = rtab + (size_t)s_ri[s] * D2 + e0;
            const uint32_t dR = smem_u32(dstR + rw * PR);
            #pragma unroll
            for (int q = 0; q < 2; q++) {
                const int c = cc + 16 * q;          // 0..31
                cp16(dR + c * 16, rr + c * 4);
            }
        }
        asm volatile("cp.async.commit_group;" ::: "memory");
    };

    const int g  = lane >> 2;
    const int t  = lane & 3;
    const int mw = (wid & 3) * 64;
    const int nw = (wid >> 2) * 64;

    float acc[4][8][4];
    #pragma unroll
    for (int i = 0; i < 4; i++)
        #pragma unroll
        for (int j = 0; j < 8; j++)
            #pragma unroll
            for (int q = 0; q < 4; q++) acc[i][j][q] = 0.f;

    load_chunk(0);
    load_chunk(1);
    load_chunk(2);

    for (int ch = 0; ch < NCH1; ch++) {
        asm volatile("cp.async.wait_group 2;" ::: "memory");
        __syncthreads();                 // also protects buffer (ch+3)&3 reuse

        load_chunk(ch + 3);

        const float* sF = sm1 + (ch & 3) * BUF_WORDS;
        const float* sR = sF + CHS1 * PF;

        const float* p0 = sF + (2 * t)     * PF;
        const float* p1 = sF + (2 * t + 1) * PF;
        const float* p2 = sF + (2 * t + 8) * PF;
        const float* p3 = sF + (2 * t + 9) * PF;
        uint32_t a[4][4];
        #pragma unroll
        for (int i = 0; i < 4; i++) {
            const int m = mw + 16 * i + g;
            a[i][0] = pack_h2(p0[m],     p1[m]);
            a[i][1] = pack_h2(p0[m + 8], p1[m + 8]);
            a[i][2] = pack_h2(p2[m],     p3[m]);
            a[i][3] = pack_h2(p2[m + 8], p3[m + 8]);
        }
        const float* q0 = sR + (2 * t)     * PR;
        const float* q1 = sR + (2 * t + 1) * PR;
        const float* q2 = sR + (2 * t + 8) * PR;
        const float* q3 = sR + (2 * t + 9) * PR;
        uint32_t bw[8][2];
        #pragma unroll
        for (int j = 0; j < 8; j++) {
            const int n = nw + 8 * j + g;
            bw[j][0] = pack_h2(q0[n], q1[n]);
            bw[j][1] = pack_h2(q2[n], q3[n]);
        }
        #pragma unroll
        for (int i = 0; i < 4; i++)
            #pragma unroll
            for (int j = 0; j < 8; j++)
                hmma(acc[i][j], a[i], bw[j]);
    }

    // epilogue: g_tp[b][d][e] fp16
    __half* tpb = g_tp + (size_t)b * KTOT;
    #pragma unroll
    for (int i = 0; i < 4; i++) {
        const int d = mw + 16 * i + g;
        #pragma unroll
        for (int j = 0; j < 8; j++) {
            const int e = e0 + nw + 8 * j + 2 * t;
            *(uint32_t*)&tpb[(size_t)d * D2 + e] =
                pack_h2(acc[i][j][0], acc[i][j][1]);
            *(uint32_t*)&tpb[(size_t)(d + 8) * D2 + e] =
                pack_h2(acc[i][j][2], acc[i][j][3]);
        }
    }
}

// ---------------------------------------------------------------------------
// Stage 2: fp16 HMMA GEMM. 8 n-tiles x 18 k-splits, 128 thr (4 warps),
// warp tile 64m x 32n. KC=64 per stage -> 57/56 stages (16x57 + 2x56 = 1024),
// halving bar.sync/loop overhead vs KC=32.
// Epilogue: atomicAdd into out (bias pre-initialized by tp_mma).
// ---------------------------------------------------------------------------
__global__ __launch_bounds__(128, 1) void gemm2_mma(
    const float* __restrict__ Wm, float* __restrict__ out)
{
    extern __shared__ char dsm[];
    const uint32_t smem_base = smem_u32(dsm);

    const int tid  = threadIdx.x;
    const int wid  = tid >> 5;
    const int lane = tid & 31;
    const int o0   = blockIdx.x * NT2;
    const int ks   = blockIdx.y;

    const int nstages = 56 + (ks < 16 ? 1 : 0);
    const size_t k_base = ((size_t)ks * 56 + (ks < 16 ? ks : 16)) * KC2;

    const int g  = lane >> 2;
    const int t  = lane & 3;
    const int n0 = wid * 32;

    // staging maps (128 threads)
    const int qa = tid & 1,  ra = tid >> 1;   // A: 64 rows, 2 thr/row, 4 chunks each
    // B: row = tid (0..127), 16 chunks each

    float acc[4][4][4];
    #pragma unroll
    for (int i = 0; i < 4; i++)
        #pragma unroll
        for (int j = 0; j < 4; j++)
            #pragma unroll
            for (int q = 0; q < 4; q++) acc[i][j][q] = 0.f;

    auto load_stage = [&](int j) {
        if (j < nstages) {
            const uint32_t sb = smem_base + (uint32_t)(j % STG) * STAGE_B;
            const size_t kf = k_base + (size_t)j * KC2;
            // A: tp rows (fp16): 64 rows x 8 chunks(16B) = 512 cp16
            #pragma unroll
            for (int q = 0; q < 4; q++) {
                const int c = qa * 4 + q;           // 0..7
                cp16(sb + (uint32_t)(ra * 144 + c * 16),
                     g_tp + (size_t)ra * KTOT + kf + c * 8);
            }
            // B: W rows (fp32): 128 rows x 16 chunks = 2048 cp16
            #pragma unroll
            for (int c = 0; c < 16; c++) {
                cp16(sb + (uint32_t)(A2_BYTES + tid * 272 + c * 16),
                     Wm + (size_t)(o0 + tid) * KTOT + kf + c * 4);
            }
        }
        asm volatile("cp.async.commit_group;" ::: "memory");
    };

    #pragma unroll
    for (int j = 0; j < PRE; j++) load_stage(j);

    for (int it = 0; it < nstages; it++) {
        asm volatile("cp.async.wait_group 1;" ::: "memory");   // PRE-1
        __syncthreads();

        load_stage(it + PRE);

        const uint32_t* sAw  = (const uint32_t*)(dsm + (it % STG) * STAGE_B);
        const float*    sB32 = (const float*)   (dsm + (it % STG) * STAGE_B + A2_BYTES);

        #pragma unroll
        for (int kc = 0; kc < 4; kc++) {
            uint32_t a[4][4];
            #pragma unroll
            for (int i = 0; i < 4; i++) {
                const int base = (16 * i + g) * 36 + t + 8 * kc;
                a[i][0] = sAw[base];
                a[i][1] = sAw[base + 288];      // +8 rows (8*36)
                a[i][2] = sAw[base + 4];
                a[i][3] = sAw[base + 292];
            }
            uint32_t bf[4][2];
            #pragma unroll
            for (int j = 0; j < 4; j++) {
                const int fb = (n0 + 8 * j + g) * 68 + 2 * t + 16 * kc;
                bf[j][0] = pack_h2(sB32[fb],     sB32[fb + 1]);
                bf[j][1] = pack_h2(sB32[fb + 8], sB32[fb + 9]);
            }
            #pragma unroll
            for (int i = 0; i < 4; i++)
                #pragma unroll
                for (int j = 0; j < 4; j++)
                    hmma(acc[i][j], a[i], bf[j]);
        }
    }

    // epilogue: accumulate into out (bias already there)
    #pragma unroll
    for (int i = 0; i < 4; i++) {
        const int b_row = i * 16 + g;
        #pragma unroll
        for (int j = 0; j < 4; j++) {
            const int col = o0 + n0 + j * 8 + 2 * t;
            float* p0 = out + (size_t)b_row * ODIM + col;
            float* p1 = out + (size_t)(b_row + 8) * ODIM + col;
            atomicAdd(p0,     acc[i][j][0]);
            atomicAdd(p0 + 1, acc[i][j][1]);
            atomicAdd(p1,     acc[i][j][2]);
            atomicAdd(p1 + 1, acc[i][j][3]);
        }
    }
}

// ---------------------------------------------------------------------------
extern "C" void kernel_launch(void* const* d_in, const int* in_sizes, int n_in,
                              void* d_out, int out_size)
{
    const int*   fillers = (const int*)  d_in[0];
    const int*   roles   = (const int*)  d_in[1];
    const float* ftab    = (const float*)d_in[2];
    const float* rtab    = (const float*)d_in[3];
    const float* Wm      = (const float*)d_in[4];
    const float* bias    = (const float*)d_in[5];
    float* out = (float*)d_out;

    cudaFuncSetAttribute(tp_mma,    cudaFuncAttributeMaxDynamicSharedMemorySize, SMEM1);
    cudaFuncSetAttribute(gemm2_mma, cudaFuncAttributeMaxDynamicSharedMemorySize, SMEM2);

    tp_mma   <<<dim3(2, BB), 256, SMEM1>>>(fillers, roles, ftab, rtab, bias, out);
    gemm2_mma<<<dim3(ODIM / NT2, KS2), 128, SMEM2>>>(Wm, out);
}

// round 17
// speedup vs baseline: 1.5992x; 1.5992x over previous
#include <cuda_runtime.h>
#include <cuda_fp16.h>
#include <stdint.h>

#define D1    256
#define D2    256
#define ODIM  1024
#define BB    64
#define SS    128
#define KTOT  (D1 * D2)       // 65536

// ---------------- stage-1 (tp) config ----------------
#define NCH1  8               // s-chunks of 16
#define CHS1  16
#define PF    260             // F smem pitch (floats), 256 d + 4 pad
#define PR    132             // R smem pitch (floats), 128 e + 4 pad
#define BUF_WORDS (CHS1 * PF + CHS1 * PR)   // 6272
#define NBUF  4
#define SMEM1 (NBUF * BUF_WORDS * 4)        // 100352 B

// ---------------- stage-2 mma config ----------------
#define KS2   18
#define NT2   128
#define KC2   64              // k per stage
#define STG   3
#define PRE   2

#define A2_BYTES  (64 * 144)           // A: 64 rows x (64 f16 = 128B + 16B pad)
#define B2_BYTES  (128 * 272)          // B: 128 rows x (64 f32 = 256B + 16B pad)
#define STAGE_B   (A2_BYTES + B2_BYTES)          // 44032
#define SMEM2     (STG * STAGE_B)                // 132096

// Device-global scratch
__device__ __half g_tp[(size_t)BB * KTOT];

// ---------------------------------------------------------------------------
// helpers
// ---------------------------------------------------------------------------
__device__ __forceinline__ uint32_t smem_u32(const void* p) {
    uint32_t a;
    asm("{ .reg .u64 t; cvta.to.shared.u64 t, %1; cvt.u32.u64 %0, t; }" : "=r"(a) : "l"(p));
    return a;
}
__device__ __forceinline__ uint32_t pack_h2(float lo, float hi) {
    uint32_t r;
    asm("cvt.rn.f16x2.f32 %0, %1, %2;" : "=r"(r) : "f"(hi), "f"(lo));
    return r;
}
__device__ __forceinline__ void cp16(uint32_t dst, const void* src) {
    asm volatile("cp.async.cg.shared.global [%0], [%1], 16;" :: "r"(dst), "l"(src));
}
__device__ __forceinline__ void hmma(float* c, const uint32_t* a, const uint32_t* b) {
    asm volatile(
        "mma.sync.aligned.m16n8k16.row.col.f32.f16.f16.f32 "
        "{%0,%1,%2,%3}, {%4,%5,%6,%7}, {%8,%9}, {%0,%1,%2,%3};"
        : "+f"(c[0]), "+f"(c[1]), "+f"(c[2]), "+f"(c[3])
        : "r"(a[0]), "r"(a[1]), "r"(a[2]), "r"(a[3]), "r"(b[0]), "r"(b[1]));
}

// ---------------------------------------------------------------------------
// Stage 1: tp[b, d, e] = sum_s F[fillers[b,s], d] * R[roles[b,s], e]
// grid (e-half=2, b=64) = 128 CTAs, 256 thr (8 warps: 4 d-tiles x 2 e-tiles).
// Prologue also initializes out[.] = bias[.] (512 floats per CTA).
// (byte-identical to the proven R14 kernel)
// ---------------------------------------------------------------------------
__global__ __launch_bounds__(256, 1) void tp_mma(
    const int*   __restrict__ fillers,
    const int*   __restrict__ roles,
    const float* __restrict__ ftab,
    const float* __restrict__ rtab,
    const float* __restrict__ bias,
    float*       __restrict__ out)
{
    extern __shared__ float sm1[];
    __shared__ int s_fi[SS];
    __shared__ int s_ri[SS];

    const int b   = blockIdx.y;
    const int e0  = blockIdx.x * 128;
    const int tid = threadIdx.x;
    const int wid  = tid >> 5;
    const int lane = tid & 31;

    if (tid < SS) s_fi[tid]      = fillers[b * SS + tid];
    else          s_ri[tid - SS] = roles[b * SS + (tid - SS)];

    // bias-init of out: 128 CTAs x 512 floats = 64K floats
    if (tid < 128) {
        const int cta = b * 2 + blockIdx.x;       // 0..127
        const int idx = cta * 512 + tid * 4;
        *(float4*)(out + idx) = *(const float4*)(bias + (idx & (ODIM - 1)));
    }
    __syncthreads();

    // staging: 16 rows/chunk, 16 thr/row; F row = 64 x 16B, R row = 32 x 16B
    const int rw = tid >> 4;     // 0..15
    const int cc = tid & 15;

    auto load_chunk = [&](int ch) {
        if (ch < NCH1) {
            float* dstF = sm1 + (ch & 3) * BUF_WORDS;
            float* dstR = dstF + CHS1 * PF;
            const int s = ch * CHS1 + rw;
            const float* fr = ftab + (size_t)s_fi[s] * D1;
            const uint32_t dF = smem_u32(dstF + rw * PF);
            #pragma unroll
            for (int q = 0; q < 4; q++) {
                const int c = cc + 16 * q;          // 0..63
                cp16(dF + c * 16, fr + c * 4);
            }
            const float* rr = rtab + (size_t)s_ri[s] * D2 + e0;
            const uint32_t dR = smem_u32(dstR + rw * PR);
            #pragma unroll
            for (int q = 0; q < 2; q++) {
                const int c = cc + 16 * q;          // 0..31
                cp16(dR + c * 16, rr + c * 4);
            }
        }
        asm volatile("cp.async.commit_group;" ::: "memory");
    };

    const int g  = lane >> 2;
    const int t  = lane & 3;
    const int mw = (wid & 3) * 64;
    const int nw = (wid >> 2) * 64;

    float acc[4][8][4];
    #pragma unroll
    for (int i = 0; i < 4; i++)
        #pragma unroll
        for (int j = 0; j < 8; j++)
            #pragma unroll
            for (int q = 0; q < 4; q++) acc[i][j][q] = 0.f;

    load_chunk(0);
    load_chunk(1);
    load_chunk(2);

    for (int ch = 0; ch < NCH1; ch++) {
        asm volatile("cp.async.wait_group 2;" ::: "memory");
        __syncthreads();                 // also protects buffer (ch+3)&3 reuse

        load_chunk(ch + 3);

        const float* sF = sm1 + (ch & 3) * BUF_WORDS;
        const float* sR = sF + CHS1 * PF;

        const float* p0 = sF + (2 * t)     * PF;
        const float* p1 = sF + (2 * t + 1) * PF;
        const float* p2 = sF + (2 * t + 8) * PF;
        const float* p3 = sF + (2 * t + 9) * PF;
        uint32_t a[4][4];
        #pragma unroll
        for (int i = 0; i < 4; i++) {
            const int m = mw + 16 * i + g;
            a[i][0] = pack_h2(p0[m],     p1[m]);
            a[i][1] = pack_h2(p0[m + 8], p1[m + 8]);
            a[i][2] = pack_h2(p2[m],     p3[m]);
            a[i][3] = pack_h2(p2[m + 8], p3[m + 8]);
        }
        const float* q0 = sR + (2 * t)     * PR;
        const float* q1 = sR + (2 * t + 1) * PR;
        const float* q2 = sR + (2 * t + 8) * PR;
        const float* q3 = sR + (2 * t + 9) * PR;
        uint32_t bw[8][2];
        #pragma unroll
        for (int j = 0; j < 8; j++) {
            const int n = nw + 8 * j + g;
            bw[j][0] = pack_h2(q0[n], q1[n]);
            bw[j][1] = pack_h2(q2[n], q3[n]);
        }
        #pragma unroll
        for (int i = 0; i < 4; i++)
            #pragma unroll
            for (int j = 0; j < 8; j++)
                hmma(acc[i][j], a[i], bw[j]);
    }

    // epilogue: g_tp[b][d][e] fp16
    __half* tpb = g_tp + (size_t)b * KTOT;
    #pragma unroll
    for (int i = 0; i < 4; i++) {
        const int d = mw + 16 * i + g;
        #pragma unroll
        for (int j = 0; j < 8; j++) {
            const int e = e0 + nw + 8 * j + 2 * t;
            *(uint32_t*)&tpb[(size_t)d * D2 + e] =
                pack_h2(acc[i][j][0], acc[i][j][1]);
            *(uint32_t*)&tpb[(size_t)(d + 8) * D2 + e] =
                pack_h2(acc[i][j][2], acc[i][j][3]);
        }
    }
}

// ---------------------------------------------------------------------------
// Stage 2: fp16 HMMA GEMM. 8 n-tiles x 18 k-splits, 128 thr (4 warps),
// warp tile 64m x 32n. KC=64 per stage -> 57/56 iterations (16x57 + 2x56).
// Staging COALESCED: warps cover contiguous 128/256B row segments.
// Epilogue: atomicAdd into out (bias pre-initialized by tp_mma).
// ---------------------------------------------------------------------------
__global__ __launch_bounds__(128, 1) void gemm2_mma(
    const float* __restrict__ Wm, float* __restrict__ out)
{
    extern __shared__ char dsm[];
    const uint32_t smem_base = smem_u32(dsm);

    const int tid  = threadIdx.x;
    const int wid  = tid >> 5;
    const int lane = tid & 31;
    const int o0   = blockIdx.x * NT2;
    const int ks   = blockIdx.y;

    const int nstages = 56 + (ks < 16 ? 1 : 0);
    const size_t k_base = ((size_t)ks * 56 + (ks < 16 ? ks : 16)) * KC2;

    const int g  = lane >> 2;
    const int t  = lane & 3;
    const int n0 = wid * 32;

    // coalesced staging maps (128 threads)
    const int c8  = tid & 7,   raA = tid >> 3;   // A: 8 chunks/row, 16 rows/pass
    const int c16 = tid & 15,  rbB = tid >> 4;   // B: 16 chunks/row, 8 rows/pass

    float acc[4][4][4];
    #pragma unroll
    for (int i = 0; i < 4; i++)
        #pragma unroll
        for (int j = 0; j < 4; j++)
            #pragma unroll
            for (int q = 0; q < 4; q++) acc[i][j][q] = 0.f;

    auto load_stage = [&](int j) {
        if (j < nstages) {
            const uint32_t sb = smem_base + (uint32_t)(j % STG) * STAGE_B;
            const size_t kf = k_base + (size_t)j * KC2;
            // A: tp rows (fp16), 64 rows x 128B; warp covers 4 rows contiguously
            #pragma unroll
            for (int p = 0; p < 4; p++) {
                const int row = raA + 16 * p;
                cp16(sb + (uint32_t)(row * 144 + c8 * 16),
                     g_tp + (size_t)row * KTOT + kf + c8 * 8);
            }
            // B: W rows (fp32), 128 rows x 256B; warp covers 2 rows contiguously
            #pragma unroll
            for (int p = 0; p < 16; p++) {
                const int row = rbB + 8 * p;
                cp16(sb + (uint32_t)(A2_BYTES + row * 272 + c16 * 16),
                     Wm + (size_t)(o0 + row) * KTOT + kf + c16 * 4);
            }
        }
        asm volatile("cp.async.commit_group;" ::: "memory");
    };

    #pragma unroll
    for (int j = 0; j < PRE; j++) load_stage(j);

    for (int it = 0; it < nstages; it++) {
        asm volatile("cp.async.wait_group 1;" ::: "memory");   // PRE-1
        __syncthreads();

        load_stage(it + PRE);

        const uint32_t* sAw  = (const uint32_t*)(dsm + (it % STG) * STAGE_B);
        const float*    sB32 = (const float*)   (dsm + (it % STG) * STAGE_B + A2_BYTES);

        #pragma unroll
        for (int kc = 0; kc < 4; kc++) {
            uint32_t a[4][4];
            #pragma unroll
            for (int i = 0; i < 4; i++) {
                const int base = (16 * i + g) * 36 + t + 8 * kc;
                a[i][0] = sAw[base];
                a[i][1] = sAw[base + 288];      // +8 rows (8*36 words)
                a[i][2] = sAw[base + 4];
                a[i][3] = sAw[base + 292];
            }
            uint32_t bf[4][2];
            #pragma unroll
            for (int j = 0; j < 4; j++) {
                const int fb = (n0 + 8 * j + g) * 68 + 2 * t + 16 * kc;
                bf[j][0] = pack_h2(sB32[fb],     sB32[fb + 1]);
                bf[j][1] = pack_h2(sB32[fb + 8], sB32[fb + 9]);
            }
            #pragma unroll
            for (int i = 0; i < 4; i++)
                #pragma unroll
                for (int j = 0; j < 4; j++)
                    hmma(acc[i][j], a[i], bf[j]);
        }
    }

    // epilogue: accumulate into out (bias already there)
    #pragma unroll
    for (int i = 0; i < 4; i++) {
        const int b_row = i * 16 + g;
        #pragma unroll
        for (int j = 0; j < 4; j++) {
            const int col = o0 + n0 + j * 8 + 2 * t;
            float* p0 = out + (size_t)b_row * ODIM + col;
            float* p1 = out + (size_t)(b_row + 8) * ODIM + col;
            atomicAdd(p0,     acc[i][j][0]);
            atomicAdd(p0 + 1, acc[i][j][1]);
            atomicAdd(p1,     acc[i][j][2]);
            atomicAdd(p1 + 1, acc[i][j][3]);
        }
    }
}

// ---------------------------------------------------------------------------
extern "C" void kernel_launch(void* const* d_in, const int* in_sizes, int n_in,
                              void* d_out, int out_size)
{
    const int*   fillers = (const int*)  d_in[0];
    const int*   roles   = (const int*)  d_in[1];
    const float* ftab    = (const float*)d_in[2];
    const float* rtab    = (const float*)d_in[3];
    const float* Wm      = (const float*)d_in[4];
    const float* bias    = (const float*)d_in[5];
    float* out = (float*)d_out;

    cudaFuncSetAttribute(tp_mma,    cudaFuncAttributeMaxDynamicSharedMemorySize, SMEM1);
    cudaFuncSetAttribute(gemm2_mma, cudaFuncAttributeMaxDynamicSharedMemorySize, SMEM2);

    tp_mma   <<<dim3(2, BB), 256, SMEM1>>>(fillers, roles, ftab, rtab, bias, out);
    gemm2_mma<<<dim3(ODIM / NT2, KS2), 128, SMEM2>>>(Wm, out);
}